// round 16
// baseline (speedup 1.0000x reference)
#include <cuda_runtime.h>
#include <cstdint>

#define B_N     1024
#define HW      49
#define XS      25088      // 512*49
#define K_TOT   2304
#define NOUT    512
#define M_TOT   50176
#define SLOTS   78         // 56 main (r*7+q) + 21 special (kh*7+q) + 1 zero
#define MT      128
#define NT      64
#define KC      32
#define NCHUNK  72         // 2304/32

// smem: per K-chunk buffer = A1,A2 [128][32] + B1,B2 [64][32] int8
#define A_TS    4096
#define B_TS    2048
#define BUFS    (2 * A_TS + 2 * B_TS)   // 12288
#define SMEM_SZ 33792                   // max(2*BUFS=24576, 64*132*4 epilogue)

// ---------------- global scratch: digit planes ----------------
__device__ int8_t g_A1[(size_t)B_N * SLOTS * 256];
__device__ int8_t g_A2[(size_t)B_N * SLOTS * 256];
__device__ int8_t g_B1[(size_t)NOUT * K_TOT];
__device__ int8_t g_B2[(size_t)NOUT * K_TOT];

// k-interleave within 32-block so each frag reg = one ld.shared.v2.u32
__device__ __forceinline__ int kperm(int kk) {
    return (kk < 16) ? ((kk >> 2) * 8 + (kk & 3))
                     : (((kk - 16) >> 2) * 8 + 4 + (kk & 3));
}
__device__ __forceinline__ void quant(float v, int8_t& d1, int8_t& d2) {
    int ai = __float2int_rn(v * 2048.0f);
    ai = max(min(ai, 16255), -16255);
    int a1 = (ai + 64) >> 7;          // arithmetic floor((ai+64)/128)
    d1 = (int8_t)a1;
    d2 = (int8_t)(ai - (a1 << 7));    // in [-64, 63]
}

// ---------------- precompute: W quantize + permute ----------------
__global__ void wsplit_kernel(const float* __restrict__ W) {
    int idx = blockIdx.x * blockDim.x + threadIdx.x;
    if (idx >= NOUT * K_TOT) return;
    int i = idx / K_TOT, kk = idx - i * K_TOT;
    int tap = kk >> 8, l = kk & 255;
    float v = W[(size_t)(l * 9 + tap) * 512 + i];     // W[l][kh][kw][i]
    int8_t d1, d2; quant(v, d1, d2);
    size_t pos = (size_t)i * K_TOT + tap * 256 + (l & ~31) + kperm(l & 31);
    g_B1[pos] = d1;
    g_B2[pos] = d2;
}

// ---------------- precompute: shifted-sum image, quantized ----------------
__global__ void mbuild_kernel(const float* __restrict__ x) {
    extern __shared__ float Xs[];
    int b = blockIdx.x, tid = threadIdx.x;
    const float4* xg = (const float4*)(x + (size_t)b * XS);
    float4* xs4 = (float4*)Xs;
    for (int i = tid; i < XS / 4; i += 256) xs4[i] = xg[i];
    __syncthreads();
    for (int idx = tid; idx < SLOTS * 256; idx += 256) {
        int slot = idx >> 8, l = idx & 255;
        float v = 0.f;
        if (slot < 56) {
            int r = slot / 7, q = slot - r * 7;
            int w = (q == 0) ? 6 : q - 1;
            if (r <= 6) v += Xs[l * 49 + r * 7 + w];
            if (r >= 1) v += Xs[(256 + l) * 49 + (r - 1) * 7 + w];
        } else if (slot < 77) {
            int s = slot - 56;
            int kh = s / 7, q = s - kh * 7;
            int w = (q == 0) ? 6 : q - 1;
            if (kh == 0)      v = Xs[(256 + l) * 49 + 35 + w];
            else if (kh == 1) v = Xs[l * 49 + w] + Xs[(256 + l) * 49 + 42 + w];
            else              v = Xs[l * 49 + 7 + w];
        }
        int8_t d1, d2; quant(v, d1, d2);
        size_t pos = (size_t)b * (SLOTS * 256) + slot * 256 + (l & ~31) + kperm(l & 31);
        g_A1[pos] = d1;
        g_A2[pos] = d2;
    }
}

// ---------------- PTX helpers ----------------
__device__ __forceinline__ uint32_t smem_u32(const void* p) {
    uint32_t a;
    asm("{ .reg .u64 t; cvta.to.shared.u64 t, %1; cvt.u32.u64 %0, t; }" : "=r"(a) : "l"(p));
    return a;
}
__device__ __forceinline__ void lds64(uint32_t& x, uint32_t& y, uint32_t addr) {
    asm volatile("ld.shared.v2.u32 {%0,%1}, [%2];" : "=r"(x), "=r"(y) : "r"(addr));
}
__device__ __forceinline__ void mma_s8(int* d, uint32_t a0, uint32_t a1,
                                       uint32_t a2, uint32_t a3,
                                       uint32_t b0, uint32_t b1) {
    asm volatile("mma.sync.aligned.m16n8k32.row.col.s32.s8.s8.s32 "
        "{%0,%1,%2,%3}, {%4,%5,%6,%7}, {%8,%9}, {%0,%1,%2,%3};"
        : "+r"(d[0]), "+r"(d[1]), "+r"(d[2]), "+r"(d[3])
        : "r"(a0), "r"(a1), "r"(a2), "r"(a3), "r"(b0), "r"(b1));
}
#define CP16(dst, src) asm volatile("cp.async.cg.shared.global [%0], [%1], 16;" :: "r"(dst), "l"(src))
#define CP_COMMIT()    asm volatile("cp.async.commit_group;" ::: "memory")
#define CP_WAIT(n)     asm volatile("cp.async.wait_group %0;" :: "n"(n) : "memory")

// ---------------- chunk loader ----------------
__device__ __forceinline__ void load_chunk(int c, int buf, uint32_t sb,
                                           int m0, int n0, int tid) {
    int tap = c >> 3, l0 = (c & 7) << 5;
    // A: 256 threads -> digit = tid>>7, row r = tid&127 (32 B each)
    {
        int dig = tid >> 7, r = tid & 127;
        int m = m0 + r;
        int b = m / 49, j = m - b * 49;
        int h = j / 7, p = j - h * 7;
        int kh = tap / 3, kw = tap - kh * 3;
        int q = p + kw - 1;
        int slot;
        if ((unsigned)q > 6u)      slot = 77;
        else if (h >= 1)           slot = (h + kh - 1) * 7 + q;
        else                       slot = 56 + kh * 7 + q;
        const int8_t* src = (dig ? g_A2 : g_A1) +
                            ((size_t)b * SLOTS + slot) * 256 + l0;
        uint32_t dst = sb + buf * BUFS + dig * A_TS + r * 32;
        CP16(dst, src);
        CP16(dst + 16, src + 16);
    }
    // B: first 128 threads -> digit = tid>>6, row r = tid&63
    if (tid < 128) {
        int dig = tid >> 6, r = tid & 63;
        const int8_t* src = (dig ? g_B2 : g_B1) +
                            (size_t)(n0 + r) * K_TOT + tap * 256 + l0;
        uint32_t dst = sb + buf * BUFS + 2 * A_TS + dig * B_TS + r * 32;
        CP16(dst, src);
        CP16(dst + 16, src + 16);
    }
}

// ---------------- main GEMM: int8 two-digit, 3 terms ----------------
// CTA tile 128x64, 8 warps = 2(M) x 4(N), warp tile 64x16.
__global__ void __launch_bounds__(256, 2)
gemm_kernel(float* __restrict__ out)
{
    extern __shared__ char smem[];
    const uint32_t sb = smem_u32(smem);
    const int tid = threadIdx.x, lane = tid & 31, wid = tid >> 5;
    const int wm = wid >> 2, wn = wid & 3;              // 2(M) x 4(N)
    const int n0 = blockIdx.x * NT, m0 = blockIdx.y * MT;

    int hh[4][2][4], md[4][2][4];
#pragma unroll
    for (int a = 0; a < 4; a++)
#pragma unroll
        for (int b = 0; b < 2; b++)
#pragma unroll
            for (int d = 0; d < 4; d++) { hh[a][b][d] = 0; md[a][b][d] = 0; }

    load_chunk(0, 0, sb, m0, n0, tid);
    CP_COMMIT();

    const int lr4 = lane >> 2;            // 0..7
    const int lc8 = (lane & 3) * 8;       // byte offset of k-pair

    for (int c = 0; c < NCHUNK; c++) {
        int buf = c & 1;
        CP_WAIT(0);
        __syncthreads();
        if (c + 1 < NCHUNK) {
            load_chunk(c + 1, buf ^ 1, sb, m0, n0, tid);
            CP_COMMIT();
        }

        uint32_t A1b = sb + buf * BUFS;
        uint32_t A2b = A1b + A_TS;
        uint32_t B1b = A1b + 2 * A_TS;
        uint32_t B2b = B1b + B_TS;

        // B fragments for this warp's 16 columns (2 n8-tiles x 2 digits)
        uint32_t b1f[2][2], b2f[2][2];
#pragma unroll
        for (int n = 0; n < 2; n++) {
            uint32_t ba = (uint32_t)(wn * 16 + n * 8 + lr4) * 32 + lc8;
            lds64(b1f[n][0], b1f[n][1], B1b + ba);
            lds64(b2f[n][0], b2f[n][1], B2b + ba);
        }
#pragma unroll
        for (int ms = 0; ms < 4; ms++) {
            uint32_t aa = (uint32_t)(wm * 64 + ms * 16 + lr4) * 32 + lc8;
            uint32_t p0, p2, p1, p3, q0, q2, q1, q3;
            lds64(p0, p2, A1b + aa);            // digit1 rows r
            lds64(p1, p3, A1b + aa + 256);      // digit1 rows r+8
            lds64(q0, q2, A2b + aa);            // digit2
            lds64(q1, q3, A2b + aa + 256);
#pragma unroll
            for (int n = 0; n < 2; n++)
                mma_s8(hh[ms][n], p0, p1, p2, p3, b1f[n][0], b1f[n][1]);   // a1*b1
#pragma unroll
            for (int n = 0; n < 2; n++)
                mma_s8(md[ms][n], p0, p1, p2, p3, b2f[n][0], b2f[n][1]);   // a1*b2
#pragma unroll
            for (int n = 0; n < 2; n++)
                mma_s8(md[ms][n], q0, q1, q2, q3, b1f[n][0], b1f[n][1]);   // a2*b1
        }
    }
    __syncthreads();

    // ---- epilogue: out = (16384*hh + 128*md) / 2^22, transpose via smem ----
    const float S = 1.0f / 4194304.0f;
    float* sD = (float*)smem;                            // [64 i][132 m]
#pragma unroll
    for (int ms = 0; ms < 4; ms++)
#pragma unroll
        for (int n = 0; n < 2; n++) {
            int m = wm * 64 + ms * 16 + lr4;
            int i = wn * 16 + n * 8 + (lane & 3) * 2;
            float v0 = (16384.f * (float)hh[ms][n][0] + 128.f * (float)md[ms][n][0]) * S;
            float v1 = (16384.f * (float)hh[ms][n][1] + 128.f * (float)md[ms][n][1]) * S;
            float v2 = (16384.f * (float)hh[ms][n][2] + 128.f * (float)md[ms][n][2]) * S;
            float v3 = (16384.f * (float)hh[ms][n][3] + 128.f * (float)md[ms][n][3]) * S;
            sD[i * 132 + m]           = v0;
            sD[(i + 1) * 132 + m]     = v1;
            sD[i * 132 + m + 8]       = v2;
            sD[(i + 1) * 132 + m + 8] = v3;
        }
    __syncthreads();
    for (int idx = tid; idx < NT * 128; idx += 256) {
        int i = idx >> 7, mm = idx & 127;
        int m = m0 + mm;
        int b = m / 49, j = m - b * 49;
        out[(size_t)b * XS + (size_t)(n0 + i) * HW + j] = sD[i * 132 + mm];
    }
}

// ---------------- launch ----------------
extern "C" void kernel_launch(void* const* d_in, const int* in_sizes, int n_in,
                              void* d_out, int out_size)
{
    const float* x = (const float*)d_in[0];
    const float* W = (const float*)d_in[1];
    if (n_in >= 2 && in_sizes[0] == 256 * 3 * 3 * 512) {   // defensive swap
        x = (const float*)d_in[1];
        W = (const float*)d_in[0];
    }

    cudaFuncSetAttribute(mbuild_kernel,
                         cudaFuncAttributeMaxDynamicSharedMemorySize, XS * 4);
    cudaFuncSetAttribute(gemm_kernel,
                         cudaFuncAttributeMaxDynamicSharedMemorySize, SMEM_SZ);

    wsplit_kernel<<<(NOUT * K_TOT + 255) / 256, 256>>>(W);
    mbuild_kernel<<<B_N, 256, XS * 4>>>(x);
    gemm_kernel<<<dim3(NOUT / NT, M_TOT / MT), 256, SMEM_SZ>>>((float*)d_out);
}

// round 17
// speedup vs baseline: 4.1163x; 4.1163x over previous
#include <cuda_runtime.h>
#include <cuda_fp16.h>
#include <cstdint>

#define B_N     1024
#define HW      49
#define XS      25088      // 512*49
#define K_TOT   2304
#define NOUT    512
#define M_TOT   50176
#define SLOTS   78         // 56 main (r*7+q) + 21 special (kh*7+q) + 1 zero
#define MT      128
#define NT      128
#define KC      32
#define NCHUNK  72         // 2304/32

// row stride in smem tiles: 64B data + 16B pad (conflict-free ldmatrix & STS)
#define RS      80
#define TS      (128 * RS)          // 10240 B per tile (A or B)
#define BUFS    (2 * TS)            // 20480 B (A + B)
#define SMEM_SZ 67584               // max(2*BUFS=40960, epilogue 128*132*4)

// ---------------- global scratch: fp16 planes ----------------
__device__ __half g_Ah[(size_t)B_N * SLOTS * 256];   // [b][slot][l]
__device__ __half g_Bh[(size_t)NOUT * K_TOT];        // [i][tap*256+l]

// ---------------- precompute: W -> fp16, permuted [i][tap*256+l] ----------------
__global__ void wsplit_kernel(const float* __restrict__ W) {
    int idx = blockIdx.x * blockDim.x + threadIdx.x;
    if (idx >= NOUT * K_TOT) return;
    int i = idx / K_TOT, kk = idx - i * K_TOT;
    int tap = kk >> 8, l = kk & 255;
    g_Bh[idx] = __float2half_rn(W[(size_t)(l * 9 + tap) * 512 + i]);  // W[l][kh][kw][i]
}

// ---------------- precompute: shifted-sum image -> fp16 ----------------
__global__ void mbuild_kernel(const float* __restrict__ x) {
    extern __shared__ float Xs[];
    int b = blockIdx.x, tid = threadIdx.x;
    const float4* xg = (const float4*)(x + (size_t)b * XS);
    float4* xs4 = (float4*)Xs;
    for (int i = tid; i < XS / 4; i += 256) xs4[i] = xg[i];
    __syncthreads();
    for (int idx = tid; idx < SLOTS * 256; idx += 256) {
        int slot = idx >> 8, l = idx & 255;
        float v = 0.f;
        if (slot < 56) {
            int r = slot / 7, q = slot - r * 7;
            int w = (q == 0) ? 6 : q - 1;
            if (r <= 6) v += Xs[l * 49 + r * 7 + w];
            if (r >= 1) v += Xs[(256 + l) * 49 + (r - 1) * 7 + w];
        } else if (slot < 77) {
            int s = slot - 56;
            int kh = s / 7, q = s - kh * 7;
            int w = (q == 0) ? 6 : q - 1;
            if (kh == 0)      v = Xs[(256 + l) * 49 + 35 + w];
            else if (kh == 1) v = Xs[l * 49 + w] + Xs[(256 + l) * 49 + 42 + w];
            else              v = Xs[l * 49 + 7 + w];
        }
        g_Ah[(size_t)b * (SLOTS * 256) + idx] = __float2half_rn(v);
    }
}

// ---------------- PTX helpers ----------------
__device__ __forceinline__ uint32_t smem_u32(const void* p) {
    uint32_t a;
    asm("{ .reg .u64 t; cvta.to.shared.u64 t, %1; cvt.u32.u64 %0, t; }" : "=r"(a) : "l"(p));
    return a;
}
__device__ __forceinline__ void ldm4(uint32_t* r, uint32_t addr) {
    asm volatile("ldmatrix.sync.aligned.m8n8.x4.shared.b16 {%0,%1,%2,%3}, [%4];"
        : "=r"(r[0]), "=r"(r[1]), "=r"(r[2]), "=r"(r[3]) : "r"(addr));
}
__device__ __forceinline__ void mma_f16(float* d, const uint32_t* a, uint32_t b0, uint32_t b1) {
    asm volatile("mma.sync.aligned.m16n8k16.row.col.f32.f16.f16.f32 "
        "{%0,%1,%2,%3}, {%4,%5,%6,%7}, {%8,%9}, {%0,%1,%2,%3};"
        : "+f"(d[0]), "+f"(d[1]), "+f"(d[2]), "+f"(d[3])
        : "r"(a[0]), "r"(a[1]), "r"(a[2]), "r"(a[3]), "r"(b0), "r"(b1));
}
#define CP16(dst, src) asm volatile("cp.async.cg.shared.global [%0], [%1], 16;" :: "r"(dst), "l"(src))
#define CP_COMMIT()    asm volatile("cp.async.commit_group;" ::: "memory")
#define CP_WAIT(n)     asm volatile("cp.async.wait_group %0;" :: "n"(n) : "memory")

// ---------------- chunk loader ----------------
// tid<128: A row tid; tid>=128: B row tid-128. 32 consecutive rows per warp
// at stride 80B -> bank-group perm (5r mod 8), conflict-free STS.
__device__ __forceinline__ void load_chunk(int c, int buf, uint32_t sb,
                                           int m0, int n0, int tid) {
    int tap = c >> 3, l0 = (c & 7) << 5;
    if (tid < 128) {
        int r = tid;
        int m = m0 + r;
        int b = m / 49, j = m - b * 49;
        int h = j / 7, p = j - h * 7;
        int kh = tap / 3, kw = tap - kh * 3;
        int q = p + kw - 1;
        int slot;
        if ((unsigned)q > 6u)      slot = 77;
        else if (h >= 1)           slot = (h + kh - 1) * 7 + q;
        else                       slot = 56 + kh * 7 + q;
        const __half* src = g_Ah + ((size_t)b * SLOTS + slot) * 256 + l0;
        uint32_t dst = sb + buf * BUFS + r * RS;
        CP16(dst,      src);
        CP16(dst + 16, src + 8);
        CP16(dst + 32, src + 16);
        CP16(dst + 48, src + 24);
    } else {
        int r = tid - 128;
        const __half* src = g_Bh + (size_t)(n0 + r) * K_TOT + tap * 256 + l0;
        uint32_t dst = sb + buf * BUFS + TS + r * RS;
        CP16(dst,      src);
        CP16(dst + 16, src + 8);
        CP16(dst + 32, src + 16);
        CP16(dst + 48, src + 24);
    }
}

// ---------------- main GEMM: M=50176, N=512, K=2304, single-pass fp16 ----------------
// CTA tile 128x128, 8 warps = 2(M) x 4(N), warp tile 64x32.
__global__ void __launch_bounds__(256, 2)
gemm_kernel(float* __restrict__ out)
{
    extern __shared__ char smem[];
    const uint32_t sb = smem_u32(smem);
    const int tid = threadIdx.x, lane = tid & 31, wid = tid >> 5;
    const int wm = wid >> 2, wn = wid & 3;              // warp grid 2(M) x 4(N)
    const int n0 = blockIdx.x * NT, m0 = blockIdx.y * MT;

    float acc[4][4][4];
#pragma unroll
    for (int a = 0; a < 4; a++)
#pragma unroll
        for (int b = 0; b < 4; b++)
#pragma unroll
            for (int d = 0; d < 4; d++) acc[a][b][d] = 0.f;

    load_chunk(0, 0, sb, m0, n0, tid);
    CP_COMMIT();

    const int lr = (lane & 7) + ((lane >> 3) & 1) * 8;  // row within 16
    const int lc = ((lane >> 4) & 1) * 16;              // 0 / 16 byte col

    for (int c = 0; c < NCHUNK; c++) {
        int buf = c & 1;
        CP_WAIT(0);          // chunk c landed
        __syncthreads();     // all warps done with buffer buf^1
        if (c + 1 < NCHUNK) {
            load_chunk(c + 1, buf ^ 1, sb, m0, n0, tid);   // overlaps compute(c)
            CP_COMMIT();
        }

        uint32_t Ab = sb + buf * BUFS;
        uint32_t Bb = Ab + TS;

#pragma unroll
        for (int s = 0; s < 2; s++) {                   // k-steps of 16
            uint32_t bf[8];
#pragma unroll
            for (int pr = 0; pr < 2; pr++) {
                uint32_t ba = (uint32_t)(wn * 32 + pr * 16 + lr) * RS + s * 32 + lc;
                ldm4(bf + pr * 4, Bb + ba);
            }
#pragma unroll
            for (int ms = 0; ms < 4; ms++) {
                uint32_t aa = (uint32_t)(wm * 64 + ms * 16 + lr) * RS + s * 32 + lc;
                uint32_t af[4];
                ldm4(af, Ab + aa);
#pragma unroll
                for (int n = 0; n < 4; n++) {
                    int pr = n >> 1, t = n & 1;
                    mma_f16(acc[ms][n], af, bf[pr * 4 + t], bf[pr * 4 + t + 2]);
                }
            }
        }
    }
    __syncthreads();

    // ---- epilogue: transpose through smem, coalesced stores ----
    float* sD = (float*)smem;                            // [128 i][132 m]
#pragma unroll
    for (int ms = 0; ms < 4; ms++)
#pragma unroll
        for (int n = 0; n < 4; n++) {
            int m = wm * 64 + ms * 16 + (lane >> 2);
            int i = wn * 32 + n * 8 + (lane & 3) * 2;
            sD[i * 132 + m]           = acc[ms][n][0];
            sD[(i + 1) * 132 + m]     = acc[ms][n][1];
            sD[i * 132 + m + 8]       = acc[ms][n][2];
            sD[(i + 1) * 132 + m + 8] = acc[ms][n][3];
        }
    __syncthreads();
    for (int idx = tid; idx < NT * 128; idx += 256) {
        int i = idx >> 7, mm = idx & 127;
        int m = m0 + mm;
        int b = m / 49, j = m - b * 49;
        out[(size_t)b * XS + (size_t)(n0 + i) * HW + j] = sD[i * 132 + mm];
    }
}

// ---------------- launch ----------------
extern "C" void kernel_launch(void* const* d_in, const int* in_sizes, int n_in,
                              void* d_out, int out_size)
{
    const float* x = (const float*)d_in[0];
    const float* W = (const float*)d_in[1];
    if (n_in >= 2 && in_sizes[0] == 256 * 3 * 3 * 512) {   // defensive swap
        x = (const float*)d_in[1];
        W = (const float*)d_in[0];
    }

    cudaFuncSetAttribute(mbuild_kernel,
                         cudaFuncAttributeMaxDynamicSharedMemorySize, XS * 4);
    cudaFuncSetAttribute(gemm_kernel,
                         cudaFuncAttributeMaxDynamicSharedMemorySize, SMEM_SZ);

    wsplit_kernel<<<(NOUT * K_TOT + 255) / 256, 256>>>(W);
    mbuild_kernel<<<B_N, 256, XS * 4>>>(x);
    gemm_kernel<<<dim3(NOUT / NT, M_TOT / MT), 256, SMEM_SZ>>>((float*)d_out);
}